// round 17
// baseline (speedup 1.0000x reference)
#include <cuda_runtime.h>
#include <cuda_bf16.h>
#include <math.h>
#include <cstdint>

// Problem constants (fixed by the dataset)
#define BATCH   32
#define DIM     4096
#define NH      32
#define NKV     8
#define HD      128
#define NREP    4          // NH / NKV
#define MAXSEQ  4096
#define NQKV    6144       // 4096 (q) + 1024 (k) + 1024 (v)
#define KC      256        // k-chunk for split-K GEMMs
#define NCH     16         // 4096 / KC
#define NSPLIT  8          // KV splits in attention
#define TSPLIT  512        // MAXSEQ / NSPLIT
#define CHT     8          // tokens per warp-chunk (double-buffered)
#define NCHUNK  64         // TSPLIT / CHT
#define WR      8          // weight rows per cp.async stage (= mma k-step)
#define NWST    (KC / WR)  // 32 stages per k-chunk
#define XSTR    260        // xs row stride (floats), ==4 mod 32: A-frags conflict-free
#define WSTR    136        // wsm row stride (floats), ==8 mod 32: B-frags conflict-free

typedef unsigned long long ull;
typedef unsigned int u32;

// Packed f32x2 helpers (Blackwell): FFMA2 only reachable via PTX fma.rn.f32x2
__device__ __forceinline__ ull pk2(float lo, float hi) {
    ull r; asm("mov.b64 %0, {%1, %2};" : "=l"(r) : "f"(lo), "f"(hi)); return r;
}
__device__ __forceinline__ ull fma2(ull a, ull b, ull c) {
    ull d; asm("fma.rn.f32x2 %0, %1, %2, %3;" : "=l"(d) : "l"(a), "l"(b), "l"(c));
    return d;
}
__device__ __forceinline__ void upk2(ull v, float& lo, float& hi) {
    asm("mov.b64 {%0, %1}, %2;" : "=f"(lo), "=f"(hi) : "l"(v));
}

// cp.async helpers
__device__ __forceinline__ u32 smem_u32(const void* p) {
    return (u32)__cvta_generic_to_shared(p);
}
__device__ __forceinline__ void cp16(u32 dst, const void* src) {
    asm volatile("cp.async.cg.shared.global [%0], [%1], 16;" :: "r"(dst), "l"(src));
}
__device__ __forceinline__ void cp_commit() {
    asm volatile("cp.async.commit_group;");
}
template<int N> __device__ __forceinline__ void cp_wait() {
    asm volatile("cp.async.wait_group %0;" :: "n"(N));
}

// tf32 helpers (3xTF32 decomposition + m16n8k8 mma)
__device__ __forceinline__ u32 to_tf32(float v) {
    u32 r; asm("cvt.rna.tf32.f32 %0, %1;" : "=r"(r) : "f"(v)); return r;
}
__device__ __forceinline__ void mma_tf32(float c[4], const u32 a[4], const u32 b[2]) {
    asm volatile(
        "mma.sync.aligned.m16n8k8.row.col.f32.tf32.tf32.f32 "
        "{%0,%1,%2,%3}, {%4,%5,%6,%7}, {%8,%9}, {%0,%1,%2,%3};"
        : "+f"(c[0]), "+f"(c[1]), "+f"(c[2]), "+f"(c[3])
        : "r"(a[0]), "r"(a[1]), "r"(a[2]), "r"(a[3]), "r"(b[0]), "r"(b[1]));
}

// Scratch (device globals; no allocation allowed)
__device__ float g_part [NCH * BATCH * NQKV];   // QKV split-K partials
__device__ float g_q    [BATCH * NH * HD];      // rope'd q
__device__ float g_k    [BATCH * NKV * HD];     // rope'd new k
__device__ float g_v    [BATCH * NKV * HD];     // new v
__device__ float g_att  [BATCH * NH * HD];      // attention output
__device__ float g_opart[NCH * BATCH * DIM];    // O-proj split-K partials
// Attention split-KV partials
__device__ float g_pm  [BATCH * NKV * NSPLIT * NREP];
__device__ float g_pl  [BATCH * NKV * NSPLIT * NREP];
__device__ float g_pacc[BATCH * NKV * NSPLIT * NREP * HD];

// ---------------------------------------------------------------------------
// Kernel A: QKV projection via tensor cores (mma.sync tf32, 3xTF32 for
// fp32-grade precision). grid (48,16), block 256 (8 warps).
// Warp = (m-tile of 16, n-group of 32). k-step 8 = one cp.async weight stage
// (3-buffer ring). Fragment loads are direct LDS with conflict-free strides
// (XSTR==4 mod 32, WSTR==8 mod 32). acc += sA*bB + bA*sB + bA*bB.
// ---------------------------------------------------------------------------
__global__ __launch_bounds__(256)
void qkv_gemm(const float* __restrict__ x,
              const float* __restrict__ wq,
              const float* __restrict__ wk,
              const float* __restrict__ wv)
{
    __shared__ float xs[32 * XSTR];          // 33.3 KB, [m][k] row-major
    __shared__ float wsm[3][WR][WSTR];       // 13.1 KB weight stages [k][n]
    const int tx = threadIdx.x;
    const int bx = blockIdx.x;
    const int by = blockIdx.y;
    const int k0 = by * KC;
    const int w  = tx >> 5;
    const int l  = tx & 31;
    const int lg = l >> 2;                   // 0..7
    const int lt = l & 3;                    // 0..3
    const int mt = w & 1;                    // m-tile (rows mt*16..+16)
    const int ncol0 = (w >> 1) * 32;         // warp n-group base (0..96)

    // stage x[32][256] into xs (row-major, stride XSTR)
    #pragma unroll
    for (int i = 0; i < 8; i++) {
        int s  = tx + i * 256;               // 0..2047 float4 slots
        int b  = s >> 6;
        int k4 = s & 63;
        float4 v = *(const float4*)&x[b * DIM + k0 + k4 * 4];
        *(float4*)&xs[b * XSTR + k4 * 4] = v;
    }

    const float* wsrc; int ncols; int colbase;
    if (bx < 32)      { wsrc = wq; ncols = 4096; colbase = bx * 128; }
    else if (bx < 40) { wsrc = wk; ncols = 1024; colbase = (bx - 32) * 128; }
    else              { wsrc = wv; ncols = 1024; colbase = (bx - 40) * 128; }

    const u32 wsb = smem_u32(&wsm[0][0][0]);
    // one cp16 per thread per stage: 8 rows x 128 cols
    auto stagew = [&](int st, int buf) {
        int r  = tx >> 5;                    // 0..7
        int cg = tx & 31;                    // 0..31
        cp16(wsb + (u32)((buf * (WR * WSTR) + r * WSTR + cg * 4) * 4),
             wsrc + (size_t)(k0 + st * WR + r) * ncols + colbase + cg * 4);
        cp_commit();
    };

    stagew(0, 0); stagew(1, 1);
    __syncthreads();                         // xs ready

    float c[4][4];                           // [n-tile][frag]
    #pragma unroll
    for (int i = 0; i < 4; i++)
        #pragma unroll
        for (int j = 0; j < 4; j++) c[i][j] = 0.f;

    int buf = 0;
    for (int st = 0; st < NWST; st++) {
        cp_wait<1>();                        // group st complete
        __syncthreads();                     // all warps done with restage target
        if (st + 2 < NWST) { int nb = buf + 2; if (nb >= 3) nb -= 3;
                             stagew(st + 2, nb); }
        else               cp_commit();      // empty group keeps wait<1> exact

        const int ks = st * WR;
        // A fragment (16x8), decomposed big/small
        u32 abig[4], asml[4];
        #pragma unroll
        for (int j = 0; j < 4; j++) {
            int row = mt * 16 + lg + (j & 1) * 8;
            int col = ks + lt + (j >> 1) * 4;
            float v = xs[row * XSTR + col];
            u32 big = to_tf32(v);
            float sm = v - __uint_as_float(big);
            abig[j] = big; asml[j] = to_tf32(sm);
        }
        // B fragments per n-tile, 3xTF32 mma
        #pragma unroll
        for (int nt = 0; nt < 4; nt++) {
            u32 bbig[2], bsml[2];
            #pragma unroll
            for (int j = 0; j < 2; j++) {
                int kk = lt + j * 4;
                int nn = ncol0 + nt * 8 + lg;
                float v = wsm[buf][kk][nn];
                u32 big = to_tf32(v);
                float sm = v - __uint_as_float(big);
                bbig[j] = big; bsml[j] = to_tf32(sm);
            }
            mma_tf32(c[nt], asml, bbig);
            mma_tf32(c[nt], abig, bsml);
            mma_tf32(c[nt], abig, bbig);
        }
        if (++buf == 3) buf = 0;
    }

    // writeback: c0,c1 -> row lg; c2,c3 -> row lg+8; cols lt*2, lt*2+1
    #pragma unroll
    for (int nt = 0; nt < 4; nt++) {
        int col  = bx * 128 + ncol0 + nt * 8 + lt * 2;
        int row0 = mt * 16 + lg;
        *(float2*)&g_part[((size_t)by * BATCH + row0)     * NQKV + col] =
            make_float2(c[nt][0], c[nt][1]);
        *(float2*)&g_part[((size_t)by * BATCH + row0 + 8) * NQKV + col] =
            make_float2(c[nt][2], c[nt][3]);
    }
}

// ---------------------------------------------------------------------------
// Kernel B: reduce split-K partials + RoPE -> g_q, g_k, g_v.
// ---------------------------------------------------------------------------
__global__ __launch_bounds__(256)
void rope_reduce(const float* __restrict__ fcos, const float* __restrict__ fsin)
{
    int idx = blockIdx.x * 256 + threadIdx.x;
    int b = idx / (NQKV / 2);
    int p = idx % (NQKV / 2);
    int col = 2 * p;

    float v0 = 0.f, v1 = 0.f;
    #pragma unroll
    for (int c = 0; c < NCH; c++) {
        float2 t = *(const float2*)&g_part[((size_t)c * BATCH + b) * NQKV + col];
        v0 += t.x; v1 += t.y;
    }

    if (col < 4096) {
        int d = col & (HD - 1);
        int dp = d >> 1;
        float c = fcos[dp], s = fsin[dp];
        g_q[b * 4096 + col]     = v0 * c - v1 * s;
        g_q[b * 4096 + col + 1] = v0 * s + v1 * c;
    } else if (col < 5120) {
        int cc = col - 4096;
        int d = cc & (HD - 1);
        int dp = d >> 1;
        float c = fcos[dp], s = fsin[dp];
        g_k[b * 1024 + cc]     = v0 * c - v1 * s;
        g_k[b * 1024 + cc + 1] = v0 * s + v1 * c;
    } else {
        int cc = col - 5120;
        g_v[b * 1024 + cc]     = v0;
        g_v[b * 1024 + cc + 1] = v1;
    }
}

// ---------------------------------------------------------------------------
// Probe pad: shifts qkv_gemm into the ncu capture slot (4th launch). No-op.
// ---------------------------------------------------------------------------
__global__ void probe_pad() {}

// ---------------------------------------------------------------------------
// Kernel C: flash-decode GQA attention, cp.async double-buffered K pipeline.
// (unchanged from R16 winner)
// ---------------------------------------------------------------------------
__global__ __launch_bounds__(256, 3)
void attention(const float* __restrict__ cache_k,
               const float* __restrict__ cache_v,
               const int* __restrict__ start_pos)
{
    __shared__ float4 ksm[8][2][CHT][32];     // 64 KB; reused for acc merge
    __shared__ float  qsm[4 * HD];            // 2 KB
    __shared__ float  psm[8][CHT * 4];        // 1 KB, warp-private
    __shared__ float  msm[8][NREP], lsm[8][NREP];

    const int hh  = blockIdx.x;               // kv head
    const int b   = blockIdx.y;
    const int spl = blockIdx.z;
    const int tx  = threadIdx.x;
    const int w   = tx >> 5;
    const int l   = tx & 31;
    const int tok = l & 7;                    // token within chunk
    const int qr  = l >> 3;                   // dim quarter (32 dims each)

    const int sp = *start_pos;                // 4095
    const int t0 = spl * TSPLIT;

    const float qscale = 1.4426950408889634f * 0.08838834764831845f;
    #pragma unroll
    for (int r = 0; r < 2; r++) {
        int o = tx + r * 256;
        qsm[o] = g_q[b * 4096 + (hh * NREP) * HD + o] * qscale;
    }
    __syncthreads();

    float m0 = -1e30f, m1 = -1e30f, m2 = -1e30f, m3 = -1e30f;
    float ls0 = 0.f, ls1 = 0.f, ls2 = 0.f, ls3 = 0.f;
    float acc[NREP][4];
    #pragma unroll
    for (int qi = 0; qi < NREP; qi++)
        #pragma unroll
        for (int j = 0; j < 4; j++) acc[qi][j] = 0.f;

    const size_t kv_bh = (size_t)b * MAXSEQ * NKV * HD + hh * HD;
    const float* gk = &g_k[(b * NKV + hh) * HD];
    const float* gv = &g_v[(b * NKV + hh) * HD];

    const u32 kbase = smem_u32(&ksm[w][0][0][0]);

    auto stage = [&](int c, int buf) {
        const int tb = t0 + c * CHT;
        #pragma unroll
        for (int r = 0; r < CHT; r++) {
            int tg = tb + r;
            const float* krow = (tg == sp) ? gk
                                           : cache_k + kv_bh + (size_t)tg * (NKV * HD);
            cp16(kbase + (u32)(((buf * CHT + r) * 32 + (l ^ r)) * 16),
                 krow + l * 4);
        }
        cp_commit();
    };

    stage(w, 0);

    for (int j = 0; j < NCHUNK / 8; j++) {
        const int c  = w + j * 8;
        const int tb = t0 + c * CHT;
        const int buf = j & 1;

        if (j < NCHUNK / 8 - 1) { stage(c + 8, buf ^ 1); cp_wait<1>(); }
        else                    { cp_wait<0>(); }
        __syncwarp();

        float s0 = 0.f, s1 = 0.f, s2 = 0.f, s3 = 0.f;
        #pragma unroll
        for (int i = 0; i < 8; i++) {
            int col = qr * 8 + i;
            float4 k4 = ksm[w][buf][tok][col ^ tok];
            float4 q0 = *(const float4*)&qsm[0 * HD + col * 4];
            float4 q1 = *(const float4*)&qsm[1 * HD + col * 4];
            float4 q2 = *(const float4*)&qsm[2 * HD + col * 4];
            float4 q3 = *(const float4*)&qsm[3 * HD + col * 4];
            s0 += k4.x*q0.x + k4.y*q0.y + k4.z*q0.z + k4.w*q0.w;
            s1 += k4.x*q1.x + k4.y*q1.y + k4.z*q1.z + k4.w*q1.w;
            s2 += k4.x*q2.x + k4.y*q2.y + k4.z*q2.z + k4.w*q2.w;
            s3 += k4.x*q3.x + k4.y*q3.y + k4.z*q3.z + k4.w*q3.w;
        }
        s0 += __shfl_xor_sync(0xffffffffu, s0, 8);
        s1 += __shfl_xor_sync(0xffffffffu, s1, 8);
        s2 += __shfl_xor_sync(0xffffffffu, s2, 8);
        s3 += __shfl_xor_sync(0xffffffffu, s3, 8);
        s0 += __shfl_xor_sync(0xffffffffu, s0, 16);
        s1 += __shfl_xor_sync(0xffffffffu, s1, 16);
        s2 += __shfl_xor_sync(0xffffffffu, s2, 16);
        s3 += __shfl_xor_sync(0xffffffffu, s3, 16);
        if (tb + tok > sp) { s0 = -1e30f; s1 = -1e30f; s2 = -1e30f; s3 = -1e30f; }

        float c0 = s0, c1 = s1, c2 = s2, c3 = s3;
        #pragma unroll
        for (int off = 4; off > 0; off >>= 1) {
            c0 = fmaxf(c0, __shfl_xor_sync(0xffffffffu, c0, off));
            c1 = fmaxf(c1, __shfl_xor_sync(0xffffffffu, c1, off));
            c2 = fmaxf(c2, __shfl_xor_sync(0xffffffffu, c2, off));
            c3 = fmaxf(c3, __shfl_xor_sync(0xffffffffu, c3, off));
        }
        if (c0 > m0) { float a = exp2f(m0 - c0); ls0 *= a;
            acc[0][0]*=a; acc[0][1]*=a; acc[0][2]*=a; acc[0][3]*=a; m0 = c0; }
        if (c1 > m1) { float a = exp2f(m1 - c1); ls1 *= a;
            acc[1][0]*=a; acc[1][1]*=a; acc[1][2]*=a; acc[1][3]*=a; m1 = c1; }
        if (c2 > m2) { float a = exp2f(m2 - c2); ls2 *= a;
            acc[2][0]*=a; acc[2][1]*=a; acc[2][2]*=a; acc[2][3]*=a; m2 = c2; }
        if (c3 > m3) { float a = exp2f(m3 - c3); ls3 *= a;
            acc[3][0]*=a; acc[3][1]*=a; acc[3][2]*=a; acc[3][3]*=a; m3 = c3; }

        float p0 = exp2f(s0 - m0), p1 = exp2f(s1 - m1);
        float p2 = exp2f(s2 - m2), p3 = exp2f(s3 - m3);
        if (qr == 0) {
            ls0 += p0; ls1 += p1; ls2 += p2; ls3 += p3;
            *(float4*)&psm[w][tok * 4] = make_float4(p0, p1, p2, p3);
        }
        __syncwarp();

        const float* vlane = cache_v + kv_bh + l * 4;
        #pragma unroll
        for (int tt = 0; tt < CHT; tt++) {
            int tg = tb + tt;
            const float* vp = (tg == sp) ? gv + l * 4
                                         : vlane + (size_t)tg * (NKV * HD);
            float4 v4 = *(const float4*)vp;
            float4 p4 = *(const float4*)&psm[w][tt * 4];
            acc[0][0] += p4.x*v4.x; acc[0][1] += p4.x*v4.y; acc[0][2] += p4.x*v4.z; acc[0][3] += p4.x*v4.w;
            acc[1][0] += p4.y*v4.x; acc[1][1] += p4.y*v4.y; acc[1][2] += p4.y*v4.z; acc[1][3] += p4.y*v4.w;
            acc[2][0] += p4.z*v4.x; acc[2][1] += p4.z*v4.y; acc[2][2] += p4.z*v4.z; acc[2][3] += p4.z*v4.w;
            acc[3][0] += p4.w*v4.x; acc[3][1] += p4.w*v4.y; acc[3][2] += p4.w*v4.z; acc[3][3] += p4.w*v4.w;
        }
        __syncwarp();
    }

    #pragma unroll
    for (int off = 16; off > 0; off >>= 1) {
        ls0 += __shfl_xor_sync(0xffffffffu, ls0, off);
        ls1 += __shfl_xor_sync(0xffffffffu, ls1, off);
        ls2 += __shfl_xor_sync(0xffffffffu, ls2, off);
        ls3 += __shfl_xor_sync(0xffffffffu, ls3, off);
    }

    __syncthreads();
    float* accs = (float*)ksm;                // [8][NREP][HD]
    #pragma unroll
    for (int qi = 0; qi < NREP; qi++)
        *(float4*)&accs[(w * NREP + qi) * HD + l * 4] =
            make_float4(acc[qi][0], acc[qi][1], acc[qi][2], acc[qi][3]);
    if (l == 0) {
        msm[w][0] = m0; msm[w][1] = m1; msm[w][2] = m2; msm[w][3] = m3;
        lsm[w][0] = ls0; lsm[w][1] = ls1; lsm[w][2] = ls2; lsm[w][3] = ls3;
    }
    __syncthreads();

    #pragma unroll
    for (int r = 0; r < 2; r++) {
        int o  = tx + r * 256;
        int qi = o >> 7;
        int d  = o & (HD - 1);
        float M = msm[0][qi];
        #pragma unroll
        for (int w2 = 1; w2 < 8; w2++) M = fmaxf(M, msm[w2][qi]);
        float num = 0.f, den = 0.f;
        #pragma unroll
        for (int w2 = 0; w2 < 8; w2++) {
            float wgt = exp2f(msm[w2][qi] - M);
            num += wgt * accs[(w2 * NREP + qi) * HD + d];
            den += wgt * lsm[w2][qi];
        }
        int pbase = ((b * NKV + hh) * NSPLIT + spl) * NREP + qi;
        g_pacc[(size_t)pbase * HD + d] = num;
        if (d == 0) { g_pl[pbase] = den; g_pm[pbase] = M; }
    }
}

// ---------------------------------------------------------------------------
// Kernel C2: merge the NSPLIT partials -> g_att. grid 256, block 512.
// ---------------------------------------------------------------------------
__global__ __launch_bounds__(512)
void att_merge()
{
    const int bh = blockIdx.x;
    const int o  = threadIdx.x;
    const int qi = o >> 7;
    const int d  = o & (HD - 1);
    const int base = bh * NSPLIT * NREP + qi;

    float M = -1e30f;
    #pragma unroll
    for (int s = 0; s < NSPLIT; s++) M = fmaxf(M, g_pm[base + s * NREP]);
    float num = 0.f, den = 0.f;
    #pragma unroll
    for (int s = 0; s < NSPLIT; s++) {
        int p = base + s * NREP;
        float wgt = exp2f(g_pm[p] - M);
        num += wgt * g_pacc[(size_t)p * HD + d];
        den += wgt * g_pl[p];
    }
    const int b = bh >> 3, h = bh & 7;
    g_att[b * 4096 + (h * NREP + qi) * HD + d] = num / den;
}

// ---------------------------------------------------------------------------
// Kernel D: output projection, split-K, batch-pair f32x2 FMA, 3-buffer
// cp.async-staged weights (unchanged from R16 winner). grid (32,16), 128.
// ---------------------------------------------------------------------------
__global__ __launch_bounds__(128)
void o_gemm(const float* __restrict__ wo)
{
    __shared__ float xs[KC * 32];         // 32 KB, transposed [k][b^sw]
    __shared__ float wsm[3][WR][128];     // 12 KB
    const int tx = threadIdx.x;
    const int bx = blockIdx.x;
    const int by = blockIdx.y;
    const int k0 = by * KC;

    #pragma unroll
    for (int i = 0; i < 16; i++) {
        int s  = tx + i * 128;
        int b  = s >> 6;
        int k4 = s & 63;
        float4 v = *(const float4*)&g_att[b * DIM + k0 + k4 * 4];
        int e = b ^ ((2 * k4) & 30);
        xs[(k4 * 4 + 0) * 32 + e] = v.x;
        xs[(k4 * 4 + 1) * 32 + e] = v.y;
        xs[(k4 * 4 + 2) * 32 + e] = v.z;
        xs[(k4 * 4 + 3) * 32 + e] = v.w;
    }

    const int q  = tx & 31;
    const int g  = tx >> 5;
    const int b0 = g * 8;
    const int gcol = bx * 128 + q * 4;
    const int colbase = bx * 128;

    const u32 wsb = smem_u32(&wsm[0][0][0]);
    auto stagew = [&](int st, int buf) {
        #pragma unroll
        for (int i = 0; i < 2; i++) {
            int r = g + i * 4;
            cp16(wsb + (u32)(((buf * WR + r) * 128 + q * 4) * 4),
                 wo + (size_t)(k0 + st * WR + r) * DIM + colbase + q * 4);
        }
        cp_commit();
    };

    stagew(0, 0); stagew(1, 1);
    __syncthreads();

    ull accp[16];
    #pragma unroll
    for (int i = 0; i < 16; i++) accp[i] = 0ULL;

    int buf = 0;
    for (int st = 0; st < NWST; st++) {
        cp_wait<1>();
        __syncthreads();
        if (st + 2 < NWST) { int nb = buf + 2; if (nb >= 3) nb -= 3;
                             stagew(st + 2, nb); }
        else               cp_commit();

        const int sw0 = (st * 4) & 30;
        #pragma unroll
        for (int r = 0; r < WR; r++) {
            const int k  = st * WR + r;
            const int sw = sw0 | ((r & 4) >> 1);
            const float* xrow = &xs[k * 32];
            ull xp0 = *(const ull*)&xrow[(b0 + 0) ^ sw];
            ull xp1 = *(const ull*)&xrow[(b0 + 2) ^ sw];
            ull xp2 = *(const ull*)&xrow[(b0 + 4) ^ sw];
            ull xp3 = *(const ull*)&xrow[(b0 + 6) ^ sw];
            float4 w4 = *(const float4*)&wsm[buf][r][q * 4];
            ull wd0 = pk2(w4.x, w4.x), wd1 = pk2(w4.y, w4.y);
            ull wd2 = pk2(w4.z, w4.z), wd3 = pk2(w4.w, w4.w);
            accp[0]  = fma2(xp0, wd0, accp[0]);
            accp[1]  = fma2(xp0, wd1, accp[1]);
            accp[2]  = fma2(xp0, wd2, accp[2]);
            accp[3]  = fma2(xp0, wd3, accp[3]);
            accp[4]  = fma2(xp1, wd0, accp[4]);
            accp[5]  = fma2(xp1, wd1, accp[5]);
            accp[6]  = fma2(xp1, wd2, accp[6]);
            accp[7]  = fma2(xp1, wd3, accp[7]);
            accp[8]  = fma2(xp2, wd0, accp[8]);
            accp[9]  = fma2(xp2, wd1, accp[9]);
            accp[10] = fma2(xp2, wd2, accp[10]);
            accp[11] = fma2(xp2, wd3, accp[11]);
            accp[12] = fma2(xp3, wd0, accp[12]);
            accp[13] = fma2(xp3, wd1, accp[13]);
            accp[14] = fma2(xp3, wd2, accp[14]);
            accp[15] = fma2(xp3, wd3, accp[15]);
        }
        if (++buf == 3) buf = 0;
    }

    #pragma unroll
    for (int p = 0; p < 4; p++) {
        float lo0, hi0, lo1, hi1, lo2, hi2, lo3, hi3;
        upk2(accp[p * 4 + 0], lo0, hi0);
        upk2(accp[p * 4 + 1], lo1, hi1);
        upk2(accp[p * 4 + 2], lo2, hi2);
        upk2(accp[p * 4 + 3], lo3, hi3);
        *(float4*)&g_opart[((size_t)by * BATCH + b0 + 2 * p)     * DIM + gcol]
            = make_float4(lo0, lo1, lo2, lo3);
        *(float4*)&g_opart[((size_t)by * BATCH + b0 + 2 * p + 1) * DIM + gcol]
            = make_float4(hi0, hi1, hi2, hi3);
    }
}

// ---------------------------------------------------------------------------
// Kernel E: reduce O partials -> d_out
// ---------------------------------------------------------------------------
__global__ __launch_bounds__(256)
void o_reduce(float* __restrict__ out)
{
    int idx = blockIdx.x * 256 + threadIdx.x;
    float v = 0.f;
    #pragma unroll
    for (int c = 0; c < NCH; c++)
        v += g_opart[(size_t)c * (BATCH * DIM) + idx];
    out[idx] = v;
}

// ---------------------------------------------------------------------------
extern "C" void kernel_launch(void* const* d_in, const int* in_sizes, int n_in,
                              void* d_out, int out_size)
{
    const float* x        = (const float*)d_in[0];
    const float* cache_k  = (const float*)d_in[1];
    const float* cache_v  = (const float*)d_in[2];
    const float* fcos     = (const float*)d_in[3];
    const float* fsin     = (const float*)d_in[4];
    const float* wq       = (const float*)d_in[5];
    const float* wk       = (const float*)d_in[6];
    const float* wv       = (const float*)d_in[7];
    const float* wo       = (const float*)d_in[8];
    const int*   sp       = (const int*)d_in[9];
    float* out            = (float*)d_out;

    // 3 probes keep qkv_gemm in the 4th-launch ncu capture slot
    probe_pad<<<1, 32>>>();
    probe_pad<<<1, 32>>>();
    probe_pad<<<1, 32>>>();
    qkv_gemm<<<dim3(48, 16), 256>>>(x, wq, wk, wv);
    rope_reduce<<<(BATCH * (NQKV / 2)) / 256, 256>>>(fcos, fsin);
    attention<<<dim3(NKV, BATCH, NSPLIT), 256>>>(cache_k, cache_v, sp);
    att_merge<<<BATCH * NKV, 512>>>();
    o_gemm<<<dim3(32, 16), 128>>>(wo);
    o_reduce<<<(BATCH * DIM) / 256, 256>>>(out);
}